// round 6
// baseline (speedup 1.0000x reference)
#include <cuda_runtime.h>

// Problem constants
#define BATCH 8
#define CDIM  512
#define NPIX  1024   // 32*32
#define NHEAD 8
#define HDIM  64

// ---------------------------------------------------------------------------
// Device-global scratch (no allocations allowed in kernel_launch).
// ---------------------------------------------------------------------------
__device__ float g_Q[BATCH * CDIM * NPIX];
__device__ float g_K[BATCH * CDIM * NPIX];
__device__ float g_V[BATCH * CDIM * NPIX];
__device__ float g_A[BATCH * CDIM * NPIX];

// ---------------------------------------------------------------------------
// tf32 mma. Operands are RAW fp32 bit patterns: sm_100 tensor cores truncate
// the low mantissa bits (CUTLASS fast-path behavior) -> ~2^-11 per-element
// error, no cvt instructions anywhere.
// ---------------------------------------------------------------------------
__device__ __forceinline__ void mma_tf32(
    float& c0, float& c1, float& c2, float& c3,
    unsigned a0, unsigned a1, unsigned a2, unsigned a3,
    unsigned b0, unsigned b1)
{
    asm volatile(
        "mma.sync.aligned.m16n8k8.row.col.f32.tf32.tf32.f32 "
        "{%0,%1,%2,%3}, {%4,%5,%6,%7}, {%8,%9}, {%0,%1,%2,%3};"
        : "+f"(c0), "+f"(c1), "+f"(c2), "+f"(c3)
        : "r"(a0), "r"(a1), "r"(a2), "r"(a3), "r"(b0), "r"(b1));
}

// ---------------------------------------------------------------------------
// 1x1-conv GEMM. Block 128(M) x 128(N), K-step 8, 8 warps 4x2, 16 mma/warp.
// k-permutation: mma k=q <-> channel 2q, k=q+4 <-> channel 2q+1 (A and B use
// the same mapping, so the k-sum is unchanged). Consequences:
//   W smem = gmem row layout [o][8 ch]  -> loader stores 1 STS.128,
//     A frags = 2x LDS.64 per 16-row tile (banks 8g+2q: conflict-free).
//   X smem [ch][n] stride 132           -> B frag banks 8q+g: conflict-free.
// No tf32 cvt (raw bits). Double-buffered, 1 barrier per k-step.
// ---------------------------------------------------------------------------
#define XSTR 132

__device__ __forceinline__ void gemm_body_tc(
    const float* __restrict__ Xb,    // [C, N] for this batch
    const float* __restrict__ W,     // [C_out, C_in] row-major
    const float* __restrict__ bias,  // [C_out]
    float* __restrict__ outb,        // [C, N]
    const float* __restrict__ residb,// [C, N] or nullptr
    int obase, int nbase)
{
    __shared__ unsigned Ws[2][128 * 8];     // [buf][o*8 + ck]
    __shared__ unsigned Xs[2][8 * XSTR];    // [buf][ck*XSTR + n]

    const int tid  = threadIdx.x;
    const int lane = tid & 31;
    const int wrp  = tid >> 5;
    const int grp  = lane >> 2;     // 0..7
    const int qid  = lane & 3;      // 0..3
    const int warpM = wrp & 3;      // 0..3  (32 rows each)
    const int warpN = wrp >> 2;     // 0..1  (64 cols each)

    float c[2][8][4];
#pragma unroll
    for (int tm = 0; tm < 2; tm++)
#pragma unroll
        for (int tn = 0; tn < 8; tn++)
#pragma unroll
            for (int k = 0; k < 4; k++) c[tm][tn][k] = 0.0f;

    // loader mapping
    const int wo = tid >> 1;            // 0..127
    const int wc = (tid & 1) * 4;       // 0 or 4
    const int xc = tid >> 5;            // 0..7
    const int xn = (tid & 31) * 4;      // 0..124

    const float* wp = W + (obase + wo) * CDIM + wc;
    const float* xp = Xb + xc * NPIX + nbase + xn;

    // Preload k-step 0 into buffer 0 (raw bits, no cvt)
    *(uint4*)&Ws[0][wo * 8 + wc] = *(const uint4*)(wp);
    *(uint4*)&Xs[0][xc * XSTR + xn] = *(const uint4*)(xp);
    __syncthreads();

    int buf = 0;
    for (int c0 = 8; c0 <= CDIM; c0 += 8) {
        const bool more = (c0 < CDIM);
        uint4 wv, xv;
        if (more) {
            wv = *(const uint4*)(wp + c0);
            xv = *(const uint4*)(xp + (size_t)c0 * NPIX);
        }

        // ---- fragment loads (LDS.64 for A, conflict-free) ----
        unsigned aH[2][4], bH[8][2];
#pragma unroll
        for (int tm = 0; tm < 2; tm++) {
            const int o = warpM * 32 + tm * 16 + grp;
            const uint2 lo = *(const uint2*)&Ws[buf][o * 8 + 2 * qid];
            const uint2 hi = *(const uint2*)&Ws[buf][(o + 8) * 8 + 2 * qid];
            aH[tm][0] = lo.x;  // (m=g,   k=q)   ch 2q
            aH[tm][1] = hi.x;  // (m=g+8, k=q)
            aH[tm][2] = lo.y;  // (m=g,   k=q+4) ch 2q+1
            aH[tm][3] = hi.y;  // (m=g+8, k=q+4)
        }
#pragma unroll
        for (int tn = 0; tn < 8; tn++) {
            const int n = warpN * 64 + tn * 8 + grp;
            bH[tn][0] = Xs[buf][(2 * qid) * XSTR + n];
            bH[tn][1] = Xs[buf][(2 * qid + 1) * XSTR + n];
        }

        // ---- 16 mma tiles ----
#pragma unroll
        for (int tm = 0; tm < 2; tm++)
#pragma unroll
            for (int tn = 0; tn < 8; tn++)
                mma_tf32(c[tm][tn][0], c[tm][tn][1], c[tm][tn][2], c[tm][tn][3],
                         aH[tm][0], aH[tm][1], aH[tm][2], aH[tm][3],
                         bH[tn][0], bH[tn][1]);

        if (more) {
            const int nb = buf ^ 1;
            *(uint4*)&Ws[nb][wo * 8 + wc] = wv;
            *(uint4*)&Xs[nb][xc * XSTR + xn] = xv;
            __syncthreads();
            buf = nb;
        }
    }

    // ---- epilogue: bias (+residual), float2 stores ----
#pragma unroll
    for (int tm = 0; tm < 2; tm++) {
        const int o0 = obase + warpM * 32 + tm * 16 + grp;
        const float bv0 = bias[o0];
        const float bv1 = bias[o0 + 8];
#pragma unroll
        for (int tn = 0; tn < 8; tn++) {
            const int n0 = nbase + warpN * 64 + tn * 8 + 2 * qid;
            float* p0 = outb + (size_t)o0 * NPIX + n0;
            float* p1 = outb + (size_t)(o0 + 8) * NPIX + n0;
            float2 v0, v1;
            v0.x = c[tm][tn][0] + bv0;
            v0.y = c[tm][tn][1] + bv0;
            v1.x = c[tm][tn][2] + bv1;
            v1.y = c[tm][tn][3] + bv1;
            if (residb != nullptr) {
                const float2 r0 = *(const float2*)(residb + (size_t)o0 * NPIX + n0);
                const float2 r1 = *(const float2*)(residb + (size_t)(o0 + 8) * NPIX + n0);
                v0.x += r0.x; v0.y += r0.y;
                v1.x += r1.x; v1.y += r1.y;
            }
            *(float2*)p0 = v0;
            *(float2*)p1 = v1;
        }
    }
}

// ---------------------------------------------------------------------------
// QKV projection: grid (N/128, C/128, 3*B). z selects {Q,K,V} x batch.
// ---------------------------------------------------------------------------
__global__ void __launch_bounds__(256, 2) qkv_kernel(
    const float* __restrict__ x,
    const float* __restrict__ Wq, const float* __restrict__ bq,
    const float* __restrict__ Wk, const float* __restrict__ bk,
    const float* __restrict__ Wv, const float* __restrict__ bv)
{
    const int z = blockIdx.z;
    const int mat = z >> 3;   // 0:Q 1:K 2:V
    const int b = z & 7;
    const float* W;
    const float* bias;
    float* out;
    if (mat == 0)      { W = Wq; bias = bq; out = g_Q; }
    else if (mat == 1) { W = Wk; bias = bk; out = g_K; }
    else               { W = Wv; bias = bv; out = g_V; }
    const size_t boff = (size_t)b * CDIM * NPIX;
    gemm_body_tc(x + boff, W, bias, out + boff, nullptr,
                 blockIdx.y * 128, blockIdx.x * 128);
}

// ---------------------------------------------------------------------------
// Output projection + residual: grid (N/128, C/128, B)
// ---------------------------------------------------------------------------
__global__ void __launch_bounds__(256, 2) oproj_kernel(
    const float* __restrict__ x,
    const float* __restrict__ Wo, const float* __restrict__ bo,
    float* __restrict__ out)
{
    const int b = blockIdx.z;
    const size_t boff = (size_t)b * CDIM * NPIX;
    gemm_body_tc(g_A + boff, Wo, bo, out + boff, x + boff,
                 blockIdx.y * 128, blockIdx.x * 128);
}

// ---------------------------------------------------------------------------
// Tensor-core flash attention, raw-bits tf32. One block = (b,h,128 i-rows),
// 8 warps; warp w owns i-rows [w*16,w*16+16) x full 64-j tile.
// k-permutations make BOTH GEMM phases use LDS.64 fragments:
//   S-phase:  k=q <-> d=8ks+2q   -> K stored TRANSPOSED Kt[j][d] stride 72;
//             frag = LDS.64 at j*72+8ks+2q (banks 8g+2q: conflict-free).
//             Q frags in regs (d-permuted), pre-scaled by 0.125.
//   PV-phase: k=q <-> j=8js+2q   -> P C-frag IS the A-frag (a={c0,c2,c1,c3},
//             raw-bit reinterpret = free); V stays in gmem layout Vs[d][j]
//             stride 72 -> plain float4 copy in, frag = LDS.64 at
//             d*72+8js+2q (conflict-free).
// Load phase: V = coalesced uint4 copy; K = transpose with d=lane store
// mapping (STS conflict-free; 16B LDGs are L2-served, L2 has headroom).
// Smem 2 x 64*72*4 = 36 KB; 2 CTAs/SM.
// ---------------------------------------------------------------------------
__global__ void __launch_bounds__(256, 2) attn_kernel_tc()
{
    __shared__ unsigned Kt[64 * 72];   // [j][d] raw fp32 bits
    __shared__ unsigned Vs[64 * 72];   // [d][j] raw fp32 bits

    const int tid  = threadIdx.x;
    const int lane = tid & 31;
    const int wrp  = tid >> 5;      // 0..7
    const int g    = lane >> 2;     // 0..7
    const int q    = lane & 3;      // 0..3

    const int bh = blockIdx.y;
    const int b  = bh >> 3;
    const int h  = bh & 7;
    const int i0 = blockIdx.x * 128;
    const int iw = i0 + wrp * 16;

    const size_t base = ((size_t)b * CDIM + h * HDIM) * NPIX;
    const float* Qp = g_Q + base;
    const float* Kp = g_K + base;
    const float* Vp = g_V + base;
    float* Ap = g_A + base;

    // ---- Q fragments in registers (d-permuted), pre-scaled by 1/8 ----
    unsigned qh[8][4];
#pragma unroll
    for (int ks = 0; ks < 8; ks++) {
        const int d0 = ks * 8 + 2 * q;
        qh[ks][0] = __float_as_uint(Qp[(size_t)d0 * NPIX + iw + g] * 0.125f);
        qh[ks][1] = __float_as_uint(Qp[(size_t)d0 * NPIX + iw + g + 8] * 0.125f);
        qh[ks][2] = __float_as_uint(Qp[(size_t)(d0 + 1) * NPIX + iw + g] * 0.125f);
        qh[ks][3] = __float_as_uint(Qp[(size_t)(d0 + 1) * NPIX + iw + g + 8] * 0.125f);
    }

    float o[8][4];
#pragma unroll
    for (int dn = 0; dn < 8; dn++)
#pragma unroll
        for (int k = 0; k < 4; k++) o[dn][k] = 0.0f;
    float rmA = -1e30f, rmB = -1e30f, rlA = 0.0f, rlB = 0.0f;

#pragma unroll 1
    for (int j0 = 0; j0 < NPIX; j0 += 64) {
        __syncthreads();   // previous iteration's readers done

        // ---- load tiles: V plain copy, K transposed ----
#pragma unroll
        for (int it = 0; it < 4; it++) {
            const int t = tid + it * 256;
            // V: [d][j] copy, coalesced LDG.128 + conflict-free STS.128
            const int dv = t >> 4;
            const int jv = (t & 15) * 4;
            *(uint4*)&Vs[dv * 72 + jv] =
                *(const uint4*)&Vp[(size_t)dv * NPIX + j0 + jv];
            // K: transpose -> Kt[j][d]; d=lane => STS conflict-free
            const int dk = t & 63;
            const int jk = (t >> 6) * 4;
            const float4 kv = *(const float4*)&Kp[(size_t)dk * NPIX + j0 + jk];
            Kt[(jk + 0) * 72 + dk] = __float_as_uint(kv.x);
            Kt[(jk + 1) * 72 + dk] = __float_as_uint(kv.y);
            Kt[(jk + 2) * 72 + dk] = __float_as_uint(kv.z);
            Kt[(jk + 3) * 72 + dk] = __float_as_uint(kv.w);
        }
        __syncthreads();

        // ---- S = Q^T K (LDS.64 B-frags) ----
        float s[8][4];
#pragma unroll
        for (int tn = 0; tn < 8; tn++)
#pragma unroll
            for (int k = 0; k < 4; k++) s[tn][k] = 0.0f;

#pragma unroll
        for (int tn = 0; tn < 8; tn++) {
            const int jrow = (g + 8 * tn) * 72 + 2 * q;
#pragma unroll
            for (int ks = 0; ks < 8; ks++) {
                const uint2 kk = *(const uint2*)&Kt[jrow + 8 * ks];
                mma_tf32(s[tn][0], s[tn][1], s[tn][2], s[tn][3],
                         qh[ks][0], qh[ks][1], qh[ks][2], qh[ks][3],
                         kk.x, kk.y);
            }
        }

        // ---- online softmax: row g (c0,c1) and row g+8 (c2,c3) ----
        float mA = -1e30f, mB = -1e30f;
#pragma unroll
        for (int tn = 0; tn < 8; tn++) {
            mA = fmaxf(mA, fmaxf(s[tn][0], s[tn][1]));
            mB = fmaxf(mB, fmaxf(s[tn][2], s[tn][3]));
        }
        mA = fmaxf(mA, __shfl_xor_sync(0xFFFFFFFFu, mA, 1));
        mA = fmaxf(mA, __shfl_xor_sync(0xFFFFFFFFu, mA, 2));
        mB = fmaxf(mB, __shfl_xor_sync(0xFFFFFFFFu, mB, 1));
        mB = fmaxf(mB, __shfl_xor_sync(0xFFFFFFFFu, mB, 2));

        const float mnA = fmaxf(rmA, mA);
        const float mnB = fmaxf(rmB, mB);
        const float ccA = __expf(rmA - mnA);
        const float ccB = __expf(rmB - mnB);
        rmA = mnA; rmB = mnB;

        float tsA = 0.0f, tsB = 0.0f;
#pragma unroll
        for (int tn = 0; tn < 8; tn++) {
            s[tn][0] = __expf(s[tn][0] - mnA);
            s[tn][1] = __expf(s[tn][1] - mnA);
            s[tn][2] = __expf(s[tn][2] - mnB);
            s[tn][3] = __expf(s[tn][3] - mnB);
            tsA += s[tn][0] + s[tn][1];
            tsB += s[tn][2] + s[tn][3];
        }
        tsA += __shfl_xor_sync(0xFFFFFFFFu, tsA, 1);
        tsA += __shfl_xor_sync(0xFFFFFFFFu, tsA, 2);
        tsB += __shfl_xor_sync(0xFFFFFFFFu, tsB, 1);
        tsB += __shfl_xor_sync(0xFFFFFFFFu, tsB, 2);
        rlA = rlA * ccA + tsA;
        rlB = rlB * ccB + tsB;

#pragma unroll
        for (int dn = 0; dn < 8; dn++) {
            o[dn][0] *= ccA; o[dn][1] *= ccA;
            o[dn][2] *= ccB; o[dn][3] *= ccB;
        }

        // ---- O += P V^T (A = P C-frag reinterpret, LDS.64 V frags) ----
#pragma unroll
        for (int js = 0; js < 8; js++) {
            const unsigned p0 = __float_as_uint(s[js][0]);  // (m=g,   k=q)
            const unsigned p1 = __float_as_uint(s[js][2]);  // (m=g+8, k=q)
            const unsigned p2 = __float_as_uint(s[js][1]);  // (m=g,   k=q+4)
            const unsigned p3 = __float_as_uint(s[js][3]);  // (m=g+8, k=q+4)
            const int jcol = 8 * js + 2 * q;
#pragma unroll
            for (int dn = 0; dn < 8; dn++) {
                const uint2 vv = *(const uint2*)&Vs[(g + 8 * dn) * 72 + jcol];
                mma_tf32(o[dn][0], o[dn][1], o[dn][2], o[dn][3],
                         p0, p1, p2, p3, vv.x, vv.y);
            }
        }
    }

    // ---- normalize + store O into g_A[d][i] ----
    const float iA = 1.0f / rlA;
    const float iB = 1.0f / rlB;
#pragma unroll
    for (int dn = 0; dn < 8; dn++) {
        const int d0 = dn * 8 + 2 * q;
        Ap[(size_t)d0 * NPIX + iw + g]           = o[dn][0] * iA;
        Ap[(size_t)(d0 + 1) * NPIX + iw + g]     = o[dn][1] * iA;
        Ap[(size_t)d0 * NPIX + iw + g + 8]       = o[dn][2] * iB;
        Ap[(size_t)(d0 + 1) * NPIX + iw + g + 8] = o[dn][3] * iB;
    }
}

// ---------------------------------------------------------------------------
// Launch: QKV proj -> attention -> output proj (+residual).
// ---------------------------------------------------------------------------
extern "C" void kernel_launch(void* const* d_in, const int* in_sizes, int n_in,
                              void* d_out, int out_size)
{
    const float* x  = (const float*)d_in[0];
    const float* Wq = (const float*)d_in[1];
    const float* bq = (const float*)d_in[2];
    const float* Wk = (const float*)d_in[3];
    const float* bk = (const float*)d_in[4];
    const float* Wv = (const float*)d_in[5];
    const float* bv = (const float*)d_in[6];
    const float* Wo = (const float*)d_in[7];
    const float* bo = (const float*)d_in[8];
    float* out = (float*)d_out;

    qkv_kernel<<<dim3(NPIX / 128, CDIM / 128, 3 * BATCH), 256>>>(
        x, Wq, bq, Wk, bk, Wv, bv);
    attn_kernel_tc<<<dim3(NPIX / 128, BATCH * NHEAD), 256>>>();
    oproj_kernel<<<dim3(NPIX / 128, CDIM / 128, BATCH), 256>>>(x, Wo, bo, out);
}

// round 7
// speedup vs baseline: 1.0032x; 1.0032x over previous
#include <cuda_runtime.h>

// Problem constants
#define BATCH 8
#define CDIM  512
#define NPIX  1024   // 32*32
#define NHEAD 8
#define HDIM  64

// ---------------------------------------------------------------------------
// Device-global scratch (no allocations allowed in kernel_launch).
// ---------------------------------------------------------------------------
__device__ float g_Q[BATCH * CDIM * NPIX];
__device__ float g_K[BATCH * CDIM * NPIX];
__device__ float g_V[BATCH * CDIM * NPIX];
__device__ float g_A[BATCH * CDIM * NPIX];

// ---------------------------------------------------------------------------
// tf32 mma with RAW fp32 bit operands (HW truncates mantissa; validated
// rel_err ~2e-5 in R6 — no cvt instructions anywhere).
// ---------------------------------------------------------------------------
__device__ __forceinline__ void mma_tf32(
    float& c0, float& c1, float& c2, float& c3,
    unsigned a0, unsigned a1, unsigned a2, unsigned a3,
    unsigned b0, unsigned b1)
{
    asm volatile(
        "mma.sync.aligned.m16n8k8.row.col.f32.tf32.tf32.f32 "
        "{%0,%1,%2,%3}, {%4,%5,%6,%7}, {%8,%9}, {%0,%1,%2,%3};"
        : "+f"(c0), "+f"(c1), "+f"(c2), "+f"(c3)
        : "r"(a0), "r"(a1), "r"(a2), "r"(a3), "r"(b0), "r"(b1));
}

// ---------------------------------------------------------------------------
// 1x1-conv GEMM. Block 128(M) x 128(N), BK=16 (2 k-substeps per smem stage ->
// 32 barriers instead of 64), 8 warps 4x2, 16 mma per substep per warp.
// k-permutation (validated R6): mma k=q <-> channel 2q, k=q+4 <-> ch 2q+1.
//   W smem: two 8-ch half-planes, row layout [o][8] -> A frags = LDS.64,
//           banks 8g+2q conflict-free (same addressing as R6).
//   X smem: [ch][n] stride 132 -> B frag banks 8q+g conflict-free.
// ---------------------------------------------------------------------------
#define XSTR 132

__device__ __forceinline__ void gemm_body_tc(
    const float* __restrict__ Xb,    // [C, N] for this batch
    const float* __restrict__ W,     // [C_out, C_in] row-major
    const float* __restrict__ bias,  // [C_out]
    float* __restrict__ outb,        // [C, N]
    const float* __restrict__ residb,// [C, N] or nullptr
    int obase, int nbase)
{
    __shared__ unsigned Ws[2][2][128 * 8];    // [buf][half][o*8 + ck]
    __shared__ unsigned Xs[2][16 * XSTR];     // [buf][ch*XSTR + n]

    const int tid  = threadIdx.x;
    const int lane = tid & 31;
    const int wrp  = tid >> 5;
    const int grp  = lane >> 2;     // 0..7
    const int qid  = lane & 3;      // 0..3
    const int warpM = wrp & 3;      // 0..3  (32 rows each)
    const int warpN = wrp >> 2;     // 0..1  (64 cols each)

    float c[2][8][4];
#pragma unroll
    for (int tm = 0; tm < 2; tm++)
#pragma unroll
        for (int tn = 0; tn < 8; tn++)
#pragma unroll
            for (int k = 0; k < 4; k++) c[tm][tn][k] = 0.0f;

    // loader mapping: W -> 2 threads/row, 8 ch each; X -> 16 ch x 8 n each
    const int wo   = tid >> 1;          // 0..127
    const int whalf= tid & 1;           // 0 or 1 (ch block of 8)
    const int xc   = tid >> 4;          // 0..15
    const int xn   = (tid & 15) * 8;    // 0..120

    const float* wp = W + (obase + wo) * CDIM + whalf * 8;
    const float* xp = Xb + xc * NPIX + nbase + xn;

    // Preload k-stage 0 into buffer 0 (raw bits)
    *(uint4*)&Ws[0][whalf][wo * 8 + 0] = *(const uint4*)(wp);
    *(uint4*)&Ws[0][whalf][wo * 8 + 4] = *(const uint4*)(wp + 4);
    *(uint4*)&Xs[0][xc * XSTR + xn]     = *(const uint4*)(xp);
    *(uint4*)&Xs[0][xc * XSTR + xn + 4] = *(const uint4*)(xp + 4);
    __syncthreads();

    int buf = 0;
    for (int c0 = 16; c0 <= CDIM; c0 += 16) {
        const bool more = (c0 < CDIM);
        uint4 wv0, wv1, xv0, xv1;
        if (more) {
            wv0 = *(const uint4*)(wp + c0);
            wv1 = *(const uint4*)(wp + c0 + 4);
            xv0 = *(const uint4*)(xp + (size_t)c0 * NPIX);
            xv1 = *(const uint4*)(xp + (size_t)c0 * NPIX + 4);
        }

        // ---- two k-substeps on current buffer ----
#pragma unroll
        for (int kk = 0; kk < 2; kk++) {
            unsigned aH[2][4], bH[8][2];
#pragma unroll
            for (int tm = 0; tm < 2; tm++) {
                const int o = warpM * 32 + tm * 16 + grp;
                const uint2 lo = *(const uint2*)&Ws[buf][kk][o * 8 + 2 * qid];
                const uint2 hi = *(const uint2*)&Ws[buf][kk][(o + 8) * 8 + 2 * qid];
                aH[tm][0] = lo.x;
                aH[tm][1] = hi.x;
                aH[tm][2] = lo.y;
                aH[tm][3] = hi.y;
            }
#pragma unroll
            for (int tn = 0; tn < 8; tn++) {
                const int n = warpN * 64 + tn * 8 + grp;
                bH[tn][0] = Xs[buf][(8 * kk + 2 * qid) * XSTR + n];
                bH[tn][1] = Xs[buf][(8 * kk + 2 * qid + 1) * XSTR + n];
            }
#pragma unroll
            for (int tm = 0; tm < 2; tm++)
#pragma unroll
                for (int tn = 0; tn < 8; tn++)
                    mma_tf32(c[tm][tn][0], c[tm][tn][1], c[tm][tn][2], c[tm][tn][3],
                             aH[tm][0], aH[tm][1], aH[tm][2], aH[tm][3],
                             bH[tn][0], bH[tn][1]);
        }

        if (more) {
            const int nb = buf ^ 1;
            *(uint4*)&Ws[nb][whalf][wo * 8 + 0] = wv0;
            *(uint4*)&Ws[nb][whalf][wo * 8 + 4] = wv1;
            *(uint4*)&Xs[nb][xc * XSTR + xn]     = xv0;
            *(uint4*)&Xs[nb][xc * XSTR + xn + 4] = xv1;
            __syncthreads();
            buf = nb;
        }
    }

    // ---- epilogue: bias (+residual), float2 stores ----
#pragma unroll
    for (int tm = 0; tm < 2; tm++) {
        const int o0 = obase + warpM * 32 + tm * 16 + grp;
        const float bv0 = bias[o0];
        const float bv1 = bias[o0 + 8];
#pragma unroll
        for (int tn = 0; tn < 8; tn++) {
            const int n0 = nbase + warpN * 64 + tn * 8 + 2 * qid;
            float* p0 = outb + (size_t)o0 * NPIX + n0;
            float* p1 = outb + (size_t)(o0 + 8) * NPIX + n0;
            float2 v0, v1;
            v0.x = c[tm][tn][0] + bv0;
            v0.y = c[tm][tn][1] + bv0;
            v1.x = c[tm][tn][2] + bv1;
            v1.y = c[tm][tn][3] + bv1;
            if (residb != nullptr) {
                const float2 r0 = *(const float2*)(residb + (size_t)o0 * NPIX + n0);
                const float2 r1 = *(const float2*)(residb + (size_t)(o0 + 8) * NPIX + n0);
                v0.x += r0.x; v0.y += r0.y;
                v1.x += r1.x; v1.y += r1.y;
            }
            *(float2*)p0 = v0;
            *(float2*)p1 = v1;
        }
    }
}

// ---------------------------------------------------------------------------
// QKV projection: grid (N/128, C/128, 3*B). z selects {Q,K,V} x batch.
// ---------------------------------------------------------------------------
__global__ void __launch_bounds__(256, 2) qkv_kernel(
    const float* __restrict__ x,
    const float* __restrict__ Wq, const float* __restrict__ bq,
    const float* __restrict__ Wk, const float* __restrict__ bk,
    const float* __restrict__ Wv, const float* __restrict__ bv)
{
    const int z = blockIdx.z;
    const int mat = z >> 3;   // 0:Q 1:K 2:V
    const int b = z & 7;
    const float* W;
    const float* bias;
    float* out;
    if (mat == 0)      { W = Wq; bias = bq; out = g_Q; }
    else if (mat == 1) { W = Wk; bias = bk; out = g_K; }
    else               { W = Wv; bias = bv; out = g_V; }
    const size_t boff = (size_t)b * CDIM * NPIX;
    gemm_body_tc(x + boff, W, bias, out + boff, nullptr,
                 blockIdx.y * 128, blockIdx.x * 128);
}

// ---------------------------------------------------------------------------
// Output projection + residual: grid (N/128, C/128, B)
// ---------------------------------------------------------------------------
__global__ void __launch_bounds__(256, 2) oproj_kernel(
    const float* __restrict__ x,
    const float* __restrict__ Wo, const float* __restrict__ bo,
    float* __restrict__ out)
{
    const int b = blockIdx.z;
    const size_t boff = (size_t)b * CDIM * NPIX;
    gemm_body_tc(g_A + boff, Wo, bo, out + boff, x + boff,
                 blockIdx.y * 128, blockIdx.x * 128);
}

// ---------------------------------------------------------------------------
// Tensor-core flash attention — R5 memory layout (both global loads
// coalesced: K plain copy, V transposed via scattered STS) + raw-bit tf32
// operands (no cvt instructions; the R6 regression was the uncoalesced K
// LDG, not the cvt removal).
// One block = (b,h,128 i-rows), 8 warps; warp w owns i-rows [16w,16w+16).
//   S-phase:  Q frags in regs (k=q <-> d=8ks+q), K in Ks[d][j] stride 72,
//             B frag = 2x LDS.32 from rows 8ks+q / 8ks+q+4.
//   PV-phase: phi k-perm (a = {c0,c2,c1,c3} reinterpret, free), V in
//             Vt[j][d] stride 68, B frag = 2x LDS.32 rows 8js+2q / +1.
// Smem 64*72*4 + 64*68*4 = 35 KB; 2 CTAs/SM.
// ---------------------------------------------------------------------------
__global__ void __launch_bounds__(256, 2) attn_kernel_tc()
{
    __shared__ unsigned Ks[64 * 72];   // [d][j] raw fp32 bits
    __shared__ unsigned Vt[64 * 68];   // [j][d] raw fp32 bits

    const int tid  = threadIdx.x;
    const int lane = tid & 31;
    const int wrp  = tid >> 5;      // 0..7
    const int g    = lane >> 2;     // 0..7
    const int q    = lane & 3;      // 0..3

    const int bh = blockIdx.y;
    const int b  = bh >> 3;
    const int h  = bh & 7;
    const int i0 = blockIdx.x * 128;
    const int iw = i0 + wrp * 16;

    const size_t base = ((size_t)b * CDIM + h * HDIM) * NPIX;
    const float* Qp = g_Q + base;
    const float* Kp = g_K + base;
    const float* Vp = g_V + base;
    float* Ap = g_A + base;

    // ---- Q fragments in registers (raw bits), pre-scaled by 1/8 ----
    unsigned qh[8][4];
#pragma unroll
    for (int ks = 0; ks < 8; ks++) {
        const int d0 = ks * 8 + q;
        qh[ks][0] = __float_as_uint(Qp[(size_t)d0 * NPIX + iw + g] * 0.125f);
        qh[ks][1] = __float_as_uint(Qp[(size_t)d0 * NPIX + iw + g + 8] * 0.125f);
        qh[ks][2] = __float_as_uint(Qp[(size_t)(d0 + 4) * NPIX + iw + g] * 0.125f);
        qh[ks][3] = __float_as_uint(Qp[(size_t)(d0 + 4) * NPIX + iw + g + 8] * 0.125f);
    }

    float o[8][4];
#pragma unroll
    for (int dn = 0; dn < 8; dn++)
#pragma unroll
        for (int k = 0; k < 4; k++) o[dn][k] = 0.0f;
    float rmA = -1e30f, rmB = -1e30f, rlA = 0.0f, rlB = 0.0f;

#pragma unroll 1
    for (int j0 = 0; j0 < NPIX; j0 += 64) {
        __syncthreads();   // previous iteration's readers done

        // ---- load tiles (both LDGs coalesced float4) ----
        for (int t = tid; t < 1024; t += 256) {
            const int d  = t >> 4;
            const int j4 = (t & 15) * 4;
            *(uint4*)&Ks[d * 72 + j4] =
                *(const uint4*)&Kp[(size_t)d * NPIX + j0 + j4];
            const float4 vv = *(const float4*)&Vp[(size_t)d * NPIX + j0 + j4];
            Vt[(j4 + 0) * 68 + d] = __float_as_uint(vv.x);
            Vt[(j4 + 1) * 68 + d] = __float_as_uint(vv.y);
            Vt[(j4 + 2) * 68 + d] = __float_as_uint(vv.z);
            Vt[(j4 + 3) * 68 + d] = __float_as_uint(vv.w);
        }
        __syncthreads();

        // ---- S = Q^T K ----
        float s[8][4];
#pragma unroll
        for (int tn = 0; tn < 8; tn++)
#pragma unroll
            for (int k = 0; k < 4; k++) s[tn][k] = 0.0f;

#pragma unroll
        for (int ks = 0; ks < 8; ks++) {
            const int r0 = (ks * 8 + q) * 72;
            const int r1 = (ks * 8 + q + 4) * 72;
#pragma unroll
            for (int tn = 0; tn < 8; tn++) {
                const int jj = g + 8 * tn;
                mma_tf32(s[tn][0], s[tn][1], s[tn][2], s[tn][3],
                         qh[ks][0], qh[ks][1], qh[ks][2], qh[ks][3],
                         Ks[r0 + jj], Ks[r1 + jj]);
            }
        }

        // ---- online softmax: row g (c0,c1) and row g+8 (c2,c3) ----
        float mA = -1e30f, mB = -1e30f;
#pragma unroll
        for (int tn = 0; tn < 8; tn++) {
            mA = fmaxf(mA, fmaxf(s[tn][0], s[tn][1]));
            mB = fmaxf(mB, fmaxf(s[tn][2], s[tn][3]));
        }
        mA = fmaxf(mA, __shfl_xor_sync(0xFFFFFFFFu, mA, 1));
        mA = fmaxf(mA, __shfl_xor_sync(0xFFFFFFFFu, mA, 2));
        mB = fmaxf(mB, __shfl_xor_sync(0xFFFFFFFFu, mB, 1));
        mB = fmaxf(mB, __shfl_xor_sync(0xFFFFFFFFu, mB, 2));

        const float mnA = fmaxf(rmA, mA);
        const float mnB = fmaxf(rmB, mB);
        const float ccA = __expf(rmA - mnA);
        const float ccB = __expf(rmB - mnB);
        rmA = mnA; rmB = mnB;

        float tsA = 0.0f, tsB = 0.0f;
#pragma unroll
        for (int tn = 0; tn < 8; tn++) {
            s[tn][0] = __expf(s[tn][0] - mnA);
            s[tn][1] = __expf(s[tn][1] - mnA);
            s[tn][2] = __expf(s[tn][2] - mnB);
            s[tn][3] = __expf(s[tn][3] - mnB);
            tsA += s[tn][0] + s[tn][1];
            tsB += s[tn][2] + s[tn][3];
        }
        tsA += __shfl_xor_sync(0xFFFFFFFFu, tsA, 1);
        tsA += __shfl_xor_sync(0xFFFFFFFFu, tsA, 2);
        tsB += __shfl_xor_sync(0xFFFFFFFFu, tsB, 1);
        tsB += __shfl_xor_sync(0xFFFFFFFFu, tsB, 2);
        rlA = rlA * ccA + tsA;
        rlB = rlB * ccB + tsB;

#pragma unroll
        for (int dn = 0; dn < 8; dn++) {
            o[dn][0] *= ccA; o[dn][1] *= ccA;
            o[dn][2] *= ccB; o[dn][3] *= ccB;
        }

        // ---- O += P V^T (A = P C-frag reinterpret via phi perm) ----
#pragma unroll
        for (int js = 0; js < 8; js++) {
            const unsigned p0 = __float_as_uint(s[js][0]);  // (m=g,   k=q)
            const unsigned p1 = __float_as_uint(s[js][2]);  // (m=g+8, k=q)
            const unsigned p2 = __float_as_uint(s[js][1]);  // (m=g,   k=q+4)
            const unsigned p3 = __float_as_uint(s[js][3]);  // (m=g+8, k=q+4)
            const int rv0 = (js * 8 + 2 * q) * 68;
            const int rv1 = (js * 8 + 2 * q + 1) * 68;
#pragma unroll
            for (int dn = 0; dn < 8; dn++) {
                const int dd = g + 8 * dn;
                mma_tf32(o[dn][0], o[dn][1], o[dn][2], o[dn][3],
                         p0, p1, p2, p3, Vt[rv0 + dd], Vt[rv1 + dd]);
            }
        }
    }

    // ---- normalize + store O into g_A[d][i] ----
    const float iA = 1.0f / rlA;
    const float iB = 1.0f / rlB;
#pragma unroll
    for (int dn = 0; dn < 8; dn++) {
        const int d0 = dn * 8 + 2 * q;
        Ap[(size_t)d0 * NPIX + iw + g]           = o[dn][0] * iA;
        Ap[(size_t)(d0 + 1) * NPIX + iw + g]     = o[dn][1] * iA;
        Ap[(size_t)d0 * NPIX + iw + g + 8]       = o[dn][2] * iB;
        Ap[(size_t)(d0 + 1) * NPIX + iw + g + 8] = o[dn][3] * iB;
    }
}

// ---------------------------------------------------------------------------
// Launch: QKV proj -> attention -> output proj (+residual).
// ---------------------------------------------------------------------------
extern "C" void kernel_launch(void* const* d_in, const int* in_sizes, int n_in,
                              void* d_out, int out_size)
{
    const float* x  = (const float*)d_in[0];
    const float* Wq = (const float*)d_in[1];
    const float* bq = (const float*)d_in[2];
    const float* Wk = (const float*)d_in[3];
    const float* bk = (const float*)d_in[4];
    const float* Wv = (const float*)d_in[5];
    const float* bv = (const float*)d_in[6];
    const float* Wo = (const float*)d_in[7];
    const float* bo = (const float*)d_in[8];
    float* out = (float*)d_out;

    qkv_kernel<<<dim3(NPIX / 128, CDIM / 128, 3 * BATCH), 256>>>(
        x, Wq, bq, Wk, bk, Wv, bv);
    attn_kernel_tc<<<dim3(NPIX / 128, BATCH * NHEAD), 256>>>();
    oproj_kernel<<<dim3(NPIX / 128, CDIM / 128, BATCH), 256>>>(x, Wo, bo, out);
}